// round 15
// baseline (speedup 1.0000x reference)
#include <cuda_runtime.h>
#include <cuda_bf16.h>
#include <cstdint>

#define E_EDGES 1024
#define N_NODES 8192
#define ZD      256
#define KK_RANK 819
#define DE_NOM  818
#define W0      (1.0f/818.0f)

// ---- scratch ----
__device__ float         g_simi[(size_t)E_EDGES * N_NODES]; // 32 MB [e][n]
__device__ unsigned      g_Hbt[256 * E_EDGES];               // bitmask [n/32][e]
__device__ unsigned      g_Hn[(size_t)N_NODES * 32];         // node-major bits [n][32]
__device__ unsigned char g_H8[(size_t)N_NODES * E_EDGES];    // s8 {0,1} H^T [n][e]
__device__ float         g_DV2[N_NODES];
__device__ int           g_nDev;
__device__ int           g_devE[E_EDGES];
__device__ int           g_devDE[E_EDGES];

// packed fp32x2 FMA (Blackwell)
__device__ __forceinline__ void ffma2(unsigned long long &d,
                                      unsigned long long a, unsigned long long b)
{
    asm volatile("fma.rn.f32x2 %0, %1, %2, %0;" : "+l"(d) : "l"(a), "l"(b));
}
__device__ __forceinline__ unsigned long long pack2(float v)
{
    unsigned long long r;
    asm("mov.b64 %0, {%1, %1};" : "=l"(r) : "f"(v));
    return r;
}
__device__ __forceinline__ unsigned lop3_xor3(unsigned a, unsigned b, unsigned c)
{
    unsigned d;
    asm("lop3.b32 %0, %1, %2, %3, 0x96;" : "=r"(d) : "r"(a), "r"(b), "r"(c));
    return d;
}
__device__ __forceinline__ unsigned lop3_maj(unsigned a, unsigned b, unsigned c)
{
    unsigned d;
    asm("lop3.b32 %0, %1, %2, %3, 0xE8;" : "=r"(d) : "r"(a), "r"(b), "r"(c));
    return d;
}
__device__ __forceinline__ uint32_t smem_u32(const void* p) {
    uint32_t a;
    asm("{ .reg .u64 t; cvta.to.shared.u64 t, %1; cvt.u32.u64 %0, t; }" : "=r"(a) : "l"(p));
    return a;
}
__device__ __forceinline__ void ldsm4(unsigned &r0, unsigned &r1,
                                      unsigned &r2, unsigned &r3, unsigned a)
{
    asm volatile("ldmatrix.sync.aligned.m8n8.x4.shared.b16 {%0,%1,%2,%3}, [%4];"
                 : "=r"(r0), "=r"(r1), "=r"(r2), "=r"(r3) : "r"(a));
}
__device__ __forceinline__ void imma(int c[4], unsigned a0, unsigned a1,
                                     unsigned a2, unsigned a3, unsigned b0, unsigned b1)
{
    asm volatile("mma.sync.aligned.m16n8k32.row.col.s32.s8.s8.s32 "
                 "{%0,%1,%2,%3},{%4,%5,%6,%7},{%8,%9},{%0,%1,%2,%3};"
                 : "+r"(c[0]), "+r"(c[1]), "+r"(c[2]), "+r"(c[3])
                 : "r"(a0), "r"(a1), "r"(a2), "r"(a3), "r"(b0), "r"(b1));
}
#define CP16(dst, src) \
    asm volatile("cp.async.cg.shared.global [%0], [%1], 16;" :: "r"(dst), "l"(src) : "memory")
#define CP_COMMIT() asm volatile("cp.async.commit_group;" ::: "memory")
#define CP_WAIT0()  asm volatile("cp.async.wait_group 0;" ::: "memory")
#define CP_WAIT1()  asm volatile("cp.async.wait_group 1;" ::: "memory")

// =====================================================================
// Kernel 1: simi = hyper_clss @ x^T  (fp32, f32x2-packed FMA)
// =====================================================================
__global__ __launch_bounds__(256) void k_simi(
    const float* __restrict__ x, const int* __restrict__ y,
    const float* __restrict__ hp)
{
    if (blockIdx.x == 0 && blockIdx.y == 0 && threadIdx.x == 0) g_nDev = 0;

    __shared__ float As[32][65];
    __shared__ float Bs[32][130];
    const int be = blockIdx.y * 64, bn = blockIdx.x * 128;
    const int tid = threadIdx.x;
    const int ty = tid >> 4, tx = tid & 15;

    unsigned long long acc2[4][4];
    #pragma unroll
    for (int i = 0; i < 4; i++)
        #pragma unroll
        for (int j = 0; j < 4; j++) acc2[i][j] = 0ull;

    for (int k0 = 0; k0 < ZD; k0 += 32) {
        #pragma unroll
        for (int p = 0; p < 2; p++) {
            int idx = tid + p * 256;
            int e = idx >> 3, k4 = (idx & 7) << 2;
            int ge = be + e;
            int row = y[ge >> 4] * 16 + (ge & 15);
            float4 v = *(const float4*)(hp + (size_t)row * ZD + k0 + k4);
            As[k4+0][e] = v.x; As[k4+1][e] = v.y; As[k4+2][e] = v.z; As[k4+3][e] = v.w;
        }
        #pragma unroll
        for (int p = 0; p < 4; p++) {
            int idx = tid + p * 256;
            int n = idx >> 3, k4 = (idx & 7) << 2;
            float4 v = *(const float4*)(x + (size_t)(bn + n) * ZD + k0 + k4);
            Bs[k4+0][n] = v.x; Bs[k4+1][n] = v.y; Bs[k4+2][n] = v.z; Bs[k4+3][n] = v.w;
        }
        __syncthreads();
        #pragma unroll
        for (int k = 0; k < 32; k++) {
            unsigned long long ad[4], bd[4];
            #pragma unroll
            for (int mi = 0; mi < 4; mi++) ad[mi] = pack2(As[k][ty + 16 * mi]);
            #pragma unroll
            for (int nj = 0; nj < 4; nj++)
                bd[nj] = *(const unsigned long long*)&Bs[k][2 * tx + 32 * nj];
            #pragma unroll
            for (int mi = 0; mi < 4; mi++)
                #pragma unroll
                for (int nj = 0; nj < 4; nj++)
                    ffma2(acc2[mi][nj], ad[mi], bd[nj]);
        }
        __syncthreads();
    }
    #pragma unroll
    for (int mi = 0; mi < 4; mi++)
        #pragma unroll
        for (int nj = 0; nj < 4; nj++) {
            unsigned lo = (unsigned)(acc2[mi][nj] & 0xFFFFFFFFull);
            unsigned hi = (unsigned)(acc2[mi][nj] >> 32);
            float2 v = make_float2(__uint_as_float(lo), __uint_as_float(hi));
            *(float2*)&g_simi[(size_t)(be + ty + 16 * mi) * N_NODES + bn + 2 * tx + 32 * nj] = v;
        }
}

// =====================================================================
// Kernel 2: exact radix select (race-free winner update)
// =====================================================================
__global__ __launch_bounds__(256) void k_select()
{
    __shared__ unsigned su[N_NODES];
    __shared__ unsigned hist[256];
    __shared__ unsigned sfx[256];
    __shared__ unsigned s_bin, s_r, s_above;

    const int e = blockIdx.x;
    const int t = threadIdx.x;
    const int lane = t & 31;
    const float* row = g_simi + (size_t)e * N_NODES;

    #pragma unroll 4
    for (int i = 0; i < 32; i++) {
        unsigned b = __float_as_uint(row[i * 256 + t]);
        su[i * 256 + t] = (b & 0x80000000u) ? ~b : (b | 0x80000000u);
    }
    if (t == 0) { s_r = KK_RANK; s_above = 0; }
    __syncthreads();

    unsigned prefix = 0, pmask = 0;
    for (int level = 0; level < 4; level++) {
        int shift = 24 - 8 * level;
        hist[t] = 0;
        __syncthreads();
        #pragma unroll 4
        for (int i = 0; i < 32; i++) {
            unsigned u = su[i * 256 + t];
            if ((u & pmask) == prefix) atomicAdd(&hist[(u >> shift) & 0xFFu], 1u);
        }
        __syncthreads();
        if (t < 32) {
            unsigned h[8], loc[8];
            #pragma unroll
            for (int j = 0; j < 8; j++) h[j] = hist[8 * lane + j];
            unsigned run = 0;
            #pragma unroll
            for (int j = 7; j >= 0; j--) { run += h[j]; loc[j] = run; }
            unsigned suf = run;
            #pragma unroll
            for (int off = 1; off < 32; off <<= 1) {
                unsigned v = __shfl_down_sync(0xFFFFFFFFu, suf, off);
                if (lane + off < 32) suf += v;
            }
            unsigned beyond = suf - run;
            #pragma unroll
            for (int j = 0; j < 8; j++) sfx[8 * lane + j] = loc[j] + beyond;
        }
        __syncthreads();

        const unsigned r_cur = s_r;
        const unsigned nxt   = (t < 255) ? sfx[t + 1] : 0u;
        const bool winner    = (sfx[t] >= r_cur) && (nxt < r_cur);
        __syncthreads();
        if (winner) {
            s_bin = (unsigned)t;
            s_r = r_cur - nxt;
            s_above += nxt;
        }
        __syncthreads();
        prefix |= (s_bin << shift);
        pmask  |= (0xFFu << shift);
        __syncthreads();
    }

    const unsigned thr = prefix;
    const unsigned de  = s_above;

    unsigned v = 0;
    #pragma unroll
    for (int b = 0; b < 32; b++)
        v |= (su[32 * t + b] > thr) ? (1u << b) : 0u;
    g_Hbt[t * E_EDGES + e] = v;

    if (t == 0 && de != DE_NOM) {
        int idx = atomicAdd(&g_nDev, 1);
        g_devE[idx] = e; g_devDE[idx] = (int)de;
    }
}

// =====================================================================
// Kernel 3: bit transpose -> g_Hn[n][32] + s8 g_H8[n][e] + DV2
// =====================================================================
__global__ __launch_bounds__(256) void k_pack_dv()
{
    const int w = blockIdx.x;           // node word 0..255
    const int t = threadIdx.x;
    const int warp = t >> 5, lane = t & 31;
    __shared__ int s_cnt[32];
    if (t < 32) s_cnt[t] = 0;
    __syncthreads();

    int myCnt = 0;
    #pragma unroll
    for (int i = 0; i < 4; i++) {
        int ew = warp + 8 * i;          // edge word 0..31
        int e  = ew * 32 + lane;
        unsigned v = g_Hbt[w * E_EDGES + e];
        #pragma unroll
        for (int b = 0; b < 32; b++) {
            // s8 write: coalesced across lanes (consecutive e)
            g_H8[(size_t)(w * 32 + b) * E_EDGES + e] = (unsigned char)((v >> b) & 1u);
            unsigned word = __ballot_sync(0xFFFFFFFFu, (v >> b) & 1u);
            if (lane == b) {
                g_Hn[(size_t)(w * 32 + b) * 32 + ew] = word;
                myCnt += __popc(word);
            }
        }
    }
    atomicAdd(&s_cnt[lane], myCnt);
    __syncthreads();
    if (t < 32) g_DV2[w * 32 + t] = rsqrtf((float)s_cnt[t]);
}

// =====================================================================
// Kernel 4: O = H^T H — HYBRID: cols 0..63 via s8 IMMA (tensor pipe),
// cols 64..127 via Harley-Seal CSA popcount (alu pipe). 512 threads.
// =====================================================================
#define TSTR 132
#define GSTR 144                         // s8 stage stride (R7-verified)
#define S8A_BYTES (128 * GSTR)           // 18432 per buffer
#define S8B_BYTES (64  * GSTR)           // 9216 per buffer

__global__ __launch_bounds__(512, 1) void k_gemm(float* __restrict__ G)
{
    int b = blockIdx.x;
    int bi = (int)(64.5f - sqrtf(64.5f * 64.5f - 2.0f * (float)b));
    while (64 * bi - bi * (bi - 1) / 2 > b) bi--;
    while (64 * (bi + 1) - (bi + 1) * bi / 2 <= b) bi++;
    const int bj = bi + (b - (64 * bi - bi * (bi - 1) / 2));

    extern __shared__ char dynsm[];
    char*     s8A = dynsm;                                   // 2 x 18432
    char*     s8B = dynsm + 2 * S8A_BYTES;                   // 2 x 9216
    unsigned* mA  = (unsigned*)(dynsm + 2 * S8A_BYTES + 2 * S8B_BYTES); // [32][128]
    unsigned* mB  = mA + 32 * 128;                           // [32][64]
    float*    sT  = (float*)dynsm;                           // [128][TSTR] (reuse)

    const int i0 = bi * 128, j0 = bj * 128;
    const int tid = threadIdx.x;
    const int lane = tid & 31, warp = tid >> 5;

    // -------- cp.async stage loader (s8 from g_H8) --------
    const unsigned s8Abase = smem_u32(s8A), s8Bbase = smem_u32(s8B);
    auto ISSUE = [&](int s, int buf) {
        const int e0 = s * 128;
        #pragma unroll
        for (int u = 0; u < 2; u++) {                        // A: 128 rows x 128B
            int idx = tid + u * 512;                         // 0..1023
            int row = idx >> 3, ch = (idx & 7) << 4;
            CP16(s8Abase + (unsigned)(buf * S8A_BYTES + row * GSTR + ch),
                 g_H8 + (size_t)(i0 + row) * E_EDGES + e0 + ch);
        }
        {                                                    // B: 64 rows x 128B
            int row = tid >> 3, ch = (tid & 7) << 4;
            CP16(s8Bbase + (unsigned)(buf * S8B_BYTES + row * GSTR + ch),
                 g_H8 + (size_t)(j0 + row) * E_EDGES + e0 + ch);
        }
        CP_COMMIT();
    };

    ISSUE(0, 0);
    ISSUE(1, 1);

    // -------- bitmask tiles (popcount half): mA full rows, mB cols 64..127 --------
    #pragma unroll
    for (int u = 0; u < 2; u++) {
        int idx = tid + u * 512;                             // 0..1023
        int r = idx >> 3, q = (idx & 7) << 2;
        uint4 va = *(const uint4*)(g_Hn + (size_t)(i0 + r) * 32 + q);
        mA[(q+0)*128 + r] = va.x; mA[(q+1)*128 + r] = va.y;
        mA[(q+2)*128 + r] = va.z; mA[(q+3)*128 + r] = va.w;
    }
    {
        int r = tid >> 3, q = (tid & 7) << 2;                // r 0..63
        uint4 vb = *(const uint4*)(g_Hn + (size_t)(j0 + 64 + r) * 32 + q);
        mB[(q+0)*64 + r] = vb.x; mB[(q+1)*64 + r] = vb.y;
        mB[(q+2)*64 + r] = vb.z; mB[(q+3)*64 + r] = vb.w;
    }

    // -------- accumulators --------
    int cI[4][4];                         // IMMA: 4 n8 frags x 4 regs
    #pragma unroll
    for (int nt = 0; nt < 4; nt++)
        #pragma unroll
        for (int q2 = 0; q2 < 4; q2++) cI[nt][q2] = 0;

    int acc[8][2];                        // popcount: rows warp+16jm, cols 64+lane+32jn
    unsigned ones[8][2];
    #pragma unroll
    for (int jm = 0; jm < 8; jm++)
        #pragma unroll
        for (int jn = 0; jn < 2; jn++) { acc[jm][jn] = 0; ones[jm][jn] = 0u; }

    // IMMA mapping: warp -> m-tile (warp>>1), col half nh = warp&1 (32 cols)
    const int mrow = (warp >> 1) * 16;
    const int nh   = warp & 1;
    const int a_row = lane & 15, a_off = (lane >> 4) << 4;
    const int b_row = ((lane >> 4) << 3) + (lane & 7);
    const int b_off = ((lane >> 3) & 1) << 4;

    // -------- mainloop: 8 stages of 128 edges --------
    for (int s = 0; s < 8; s++) {
        if (s == 7) CP_WAIT0(); else CP_WAIT1();
        __syncthreads();
        const int buf = s & 1;

        // IMMA: 4 k32 steps on s8 stage  +  CSA: 2 double-steps on bitmasks
        #pragma unroll
        for (int half = 0; half < 2; half++) {
            // --- IMMA 2 k32 steps ---
            #pragma unroll
            for (int kq = 0; kq < 2; kq++) {
                int koff = (half * 2 + kq) * 32;
                unsigned af[4];
                ldsm4(af[0], af[1], af[2], af[3],
                      s8Abase + (unsigned)(buf * S8A_BYTES + (mrow + a_row) * GSTR + koff + a_off));
                unsigned bf[2][4];
                #pragma unroll
                for (int h = 0; h < 2; h++)
                    ldsm4(bf[h][0], bf[h][1], bf[h][2], bf[h][3],
                          s8Bbase + (unsigned)(buf * S8B_BYTES +
                              (nh * 32 + h * 16 + b_row) * GSTR + koff + b_off));
                #pragma unroll
                for (int nt = 0; nt < 4; nt++) {
                    int h = nt >> 1, s2 = (nt & 1) << 1;
                    imma(cI[nt], af[0], af[1], af[2], af[3], bf[h][s2], bf[h][s2 + 1]);
                }
            }
            // --- CSA double-step over ews 4s+2*half, +1 ---
            {
                int ew = 4 * s + 2 * half;
                unsigned a0[8], a1[8], b0[2], b1[2];
                #pragma unroll
                for (int jm = 0; jm < 8; jm++) {
                    a0[jm] = mA[ ew      * 128 + warp + 16 * jm];
                    a1[jm] = mA[(ew + 1) * 128 + warp + 16 * jm];
                }
                #pragma unroll
                for (int jn = 0; jn < 2; jn++) {
                    b0[jn] = mB[ ew      * 64 + lane + 32 * jn];
                    b1[jn] = mB[(ew + 1) * 64 + lane + 32 * jn];
                }
                #pragma unroll
                for (int jm = 0; jm < 8; jm++)
                    #pragma unroll
                    for (int jn = 0; jn < 2; jn++) {
                        unsigned t0 = a0[jm] & b0[jn];
                        unsigned t1 = a1[jm] & b1[jn];
                        unsigned o  = ones[jm][jn];
                        ones[jm][jn] = lop3_xor3(o, t0, t1);
                        acc[jm][jn] += __popc(lop3_maj(o, t0, t1));
                    }
            }
        }
        __syncthreads();
        if (s + 2 < 8) ISSUE(s + 2, buf);
    }
    #pragma unroll
    for (int jm = 0; jm < 8; jm++)
        #pragma unroll
        for (int jn = 0; jn < 2; jn++)
            acc[jm][jn] = 2 * acc[jm][jn] + __popc(ones[jm][jn]);

    __syncthreads();   // all smem reads done before sT reuse

    // -------- epilogue --------
    const bool offd = (bi != bj);
    // IMMA half: cols nh*32 + nt*8 + 2q
    {
        int r = lane >> 2, q2 = lane & 3;
        int rl0 = mrow + r, rl1 = rl0 + 8;
        float s0 = g_DV2[i0 + rl0] * W0, s1 = g_DV2[i0 + rl1] * W0;
        #pragma unroll
        for (int nt = 0; nt < 4; nt++) {
            int cl = nh * 32 + nt * 8 + 2 * q2;
            float t0 = g_DV2[j0 + cl], t1 = g_DV2[j0 + cl + 1];
            float v00 = (float)cI[nt][0] * s0 * t0;
            float v01 = (float)cI[nt][1] * s0 * t1;
            float v10 = (float)cI[nt][2] * s1 * t0;
            float v11 = (float)cI[nt][3] * s1 * t1;
            *(float2*)&G[(size_t)(i0 + rl0) * N_NODES + j0 + cl] = make_float2(v00, v01);
            *(float2*)&G[(size_t)(i0 + rl1) * N_NODES + j0 + cl] = make_float2(v10, v11);
            if (offd) {
                sT[(cl    ) * TSTR + rl0] = v00;
                sT[(cl + 1) * TSTR + rl0] = v01;
                sT[(cl    ) * TSTR + rl1] = v10;
                sT[(cl + 1) * TSTR + rl1] = v11;
            }
        }
    }
    // popcount half: cols 64 + lane + 32jn, rows warp + 16jm
    #pragma unroll
    for (int jm = 0; jm < 8; jm++) {
        int rl = warp + 16 * jm;
        float si = g_DV2[i0 + rl] * W0;
        #pragma unroll
        for (int jn = 0; jn < 2; jn++) {
            int cl = 64 + lane + 32 * jn;
            float v = (float)acc[jm][jn] * si * g_DV2[j0 + cl];
            G[(size_t)(i0 + rl) * N_NODES + j0 + cl] = v;
            if (offd) sT[cl * TSTR + rl] = v;
        }
    }
    if (offd) {
        __syncthreads();
        #pragma unroll
        for (int t2 = tid; t2 < 4096; t2 += 512) {
            int jr = t2 >> 5, ic = (t2 & 31) << 2;
            float4 v = *(const float4*)&sT[jr * TSTR + ic];
            *(float4*)&G[(size_t)(j0 + jr) * N_NODES + i0 + ic] = v;
        }
    }
}

// =====================================================================
// Kernel 5: exact correction for deviant edges (de != 818); usually no-op
// =====================================================================
__global__ __launch_bounds__(256) void k_fix(float* __restrict__ G)
{
    const int d = blockIdx.x;
    if (d >= g_nDev) return;
    const int e = g_devE[d];
    const int de = g_devDE[d];
    const float delta = 1.0f / (float)de - W0;

    __shared__ int mem[2048];
    __shared__ int cnt;
    if (threadIdx.x == 0) cnt = 0;
    __syncthreads();
    for (int n = threadIdx.x; n < N_NODES; n += 256)
        if ((g_Hn[(size_t)n * 32 + (e >> 5)] >> (e & 31)) & 1u) {
            int p = atomicAdd(&cnt, 1); mem[p] = n;
        }
    __syncthreads();
    const int m = cnt;
    for (int idx = threadIdx.x; idx < m * m; idx += 256) {
        int i = mem[idx / m], j = mem[idx % m];
        atomicAdd(&G[(size_t)i * N_NODES + j], delta * g_DV2[i] * g_DV2[j]);
    }
}

// =====================================================================
extern "C" void kernel_launch(void* const* d_in, const int* in_sizes, int n_in,
                              void* d_out, int out_size)
{
    const float* x  = (const float*)d_in[0];
    const int*   y  = (const int*)d_in[1];
    const float* hp = (const float*)d_in[2];
    float* out = (float*)d_out;

    const int smemBytes = 2 * S8A_BYTES + 2 * S8B_BYTES + 32 * 128 * 4 + 32 * 64 * 4; // 79872
    cudaFuncSetAttribute(k_gemm, cudaFuncAttributeMaxDynamicSharedMemorySize, smemBytes);

    k_simi<<<dim3(N_NODES / 128, E_EDGES / 64), 256>>>(x, y, hp);
    k_select<<<E_EDGES, 256>>>();
    k_pack_dv<<<256, 256>>>();
    k_gemm<<<2080, 512, smemBytes>>>(out);
    k_fix<<<128, 256>>>(out);

    size_t gElems = (size_t)N_NODES * N_NODES;
    if ((size_t)out_size >= gElems + (size_t)N_NODES * ZD) {
        cudaMemcpyAsync(out + gElems, x, (size_t)N_NODES * ZD * sizeof(float),
                        cudaMemcpyDeviceToDevice);
    }
}

// round 16
// speedup vs baseline: 1.0130x; 1.0130x over previous
#include <cuda_runtime.h>
#include <cuda_bf16.h>
#include <cstdint>

#define E_EDGES 1024
#define N_NODES 8192
#define ZD      256
#define KK_RANK 819
#define DE_NOM  818
#define W0      (1.0f/818.0f)

// ---- scratch ----
__device__ float         g_simi[(size_t)E_EDGES * N_NODES]; // 32 MB [e][n]
__device__ unsigned      g_Hbt[256 * E_EDGES];               // bitmask [n/32][e]
__device__ unsigned      g_Hn[(size_t)N_NODES * 32];         // node-major bits [n][32]
__device__ unsigned char g_H8[(size_t)N_NODES * E_EDGES];    // s8 {0,1} H^T [n][e]
__device__ float         g_DV2[N_NODES];
__device__ int           g_nDev;
__device__ int           g_devE[E_EDGES];
__device__ int           g_devDE[E_EDGES];

// packed fp32x2 FMA (Blackwell)
__device__ __forceinline__ void ffma2(unsigned long long &d,
                                      unsigned long long a, unsigned long long b)
{
    asm volatile("fma.rn.f32x2 %0, %1, %2, %0;" : "+l"(d) : "l"(a), "l"(b));
}
__device__ __forceinline__ unsigned long long pack2(float v)
{
    unsigned long long r;
    asm("mov.b64 %0, {%1, %1};" : "=l"(r) : "f"(v));
    return r;
}
__device__ __forceinline__ unsigned lop3_xor3(unsigned a, unsigned b, unsigned c)
{
    unsigned d;
    asm("lop3.b32 %0, %1, %2, %3, 0x96;" : "=r"(d) : "r"(a), "r"(b), "r"(c));
    return d;
}
__device__ __forceinline__ unsigned lop3_maj(unsigned a, unsigned b, unsigned c)
{
    unsigned d;
    asm("lop3.b32 %0, %1, %2, %3, 0xE8;" : "=r"(d) : "r"(a), "r"(b), "r"(c));
    return d;
}
__device__ __forceinline__ uint32_t smem_u32(const void* p) {
    uint32_t a;
    asm("{ .reg .u64 t; cvta.to.shared.u64 t, %1; cvt.u32.u64 %0, t; }" : "=r"(a) : "l"(p));
    return a;
}
__device__ __forceinline__ void ldsm4(unsigned &r0, unsigned &r1,
                                      unsigned &r2, unsigned &r3, unsigned a)
{
    asm volatile("ldmatrix.sync.aligned.m8n8.x4.shared.b16 {%0,%1,%2,%3}, [%4];"
                 : "=r"(r0), "=r"(r1), "=r"(r2), "=r"(r3) : "r"(a));
}
__device__ __forceinline__ void imma(int c[4], unsigned a0, unsigned a1,
                                     unsigned a2, unsigned a3, unsigned b0, unsigned b1)
{
    asm volatile("mma.sync.aligned.m16n8k32.row.col.s32.s8.s8.s32 "
                 "{%0,%1,%2,%3},{%4,%5,%6,%7},{%8,%9},{%0,%1,%2,%3};"
                 : "+r"(c[0]), "+r"(c[1]), "+r"(c[2]), "+r"(c[3])
                 : "r"(a0), "r"(a1), "r"(a2), "r"(a3), "r"(b0), "r"(b1));
}
#define CP16(dst, src) \
    asm volatile("cp.async.cg.shared.global [%0], [%1], 16;" :: "r"(dst), "l"(src) : "memory")
#define CP_COMMIT() asm volatile("cp.async.commit_group;" ::: "memory")
#define CP_WAIT0()  asm volatile("cp.async.wait_group 0;" ::: "memory")
#define CP_WAIT1()  asm volatile("cp.async.wait_group 1;" ::: "memory")

// =====================================================================
// Kernel 1: simi = hyper_clss @ x^T  (fp32, f32x2-packed FMA)
// =====================================================================
__global__ __launch_bounds__(256) void k_simi(
    const float* __restrict__ x, const int* __restrict__ y,
    const float* __restrict__ hp)
{
    if (blockIdx.x == 0 && blockIdx.y == 0 && threadIdx.x == 0) g_nDev = 0;

    __shared__ float As[32][65];
    __shared__ float Bs[32][130];
    const int be = blockIdx.y * 64, bn = blockIdx.x * 128;
    const int tid = threadIdx.x;
    const int ty = tid >> 4, tx = tid & 15;

    unsigned long long acc2[4][4];
    #pragma unroll
    for (int i = 0; i < 4; i++)
        #pragma unroll
        for (int j = 0; j < 4; j++) acc2[i][j] = 0ull;

    for (int k0 = 0; k0 < ZD; k0 += 32) {
        #pragma unroll
        for (int p = 0; p < 2; p++) {
            int idx = tid + p * 256;
            int e = idx >> 3, k4 = (idx & 7) << 2;
            int ge = be + e;
            int row = y[ge >> 4] * 16 + (ge & 15);
            float4 v = *(const float4*)(hp + (size_t)row * ZD + k0 + k4);
            As[k4+0][e] = v.x; As[k4+1][e] = v.y; As[k4+2][e] = v.z; As[k4+3][e] = v.w;
        }
        #pragma unroll
        for (int p = 0; p < 4; p++) {
            int idx = tid + p * 256;
            int n = idx >> 3, k4 = (idx & 7) << 2;
            float4 v = *(const float4*)(x + (size_t)(bn + n) * ZD + k0 + k4);
            Bs[k4+0][n] = v.x; Bs[k4+1][n] = v.y; Bs[k4+2][n] = v.z; Bs[k4+3][n] = v.w;
        }
        __syncthreads();
        #pragma unroll
        for (int k = 0; k < 32; k++) {
            unsigned long long ad[4], bd[4];
            #pragma unroll
            for (int mi = 0; mi < 4; mi++) ad[mi] = pack2(As[k][ty + 16 * mi]);
            #pragma unroll
            for (int nj = 0; nj < 4; nj++)
                bd[nj] = *(const unsigned long long*)&Bs[k][2 * tx + 32 * nj];
            #pragma unroll
            for (int mi = 0; mi < 4; mi++)
                #pragma unroll
                for (int nj = 0; nj < 4; nj++)
                    ffma2(acc2[mi][nj], ad[mi], bd[nj]);
        }
        __syncthreads();
    }
    #pragma unroll
    for (int mi = 0; mi < 4; mi++)
        #pragma unroll
        for (int nj = 0; nj < 4; nj++) {
            unsigned lo = (unsigned)(acc2[mi][nj] & 0xFFFFFFFFull);
            unsigned hi = (unsigned)(acc2[mi][nj] >> 32);
            float2 v = make_float2(__uint_as_float(lo), __uint_as_float(hi));
            *(float2*)&g_simi[(size_t)(be + ty + 16 * mi) * N_NODES + bn + 2 * tx + 32 * nj] = v;
        }
}

// =====================================================================
// Kernel 2: exact radix select (race-free winner update)
// =====================================================================
__global__ __launch_bounds__(256) void k_select()
{
    __shared__ unsigned su[N_NODES];
    __shared__ unsigned hist[256];
    __shared__ unsigned sfx[256];
    __shared__ unsigned s_bin, s_r, s_above;

    const int e = blockIdx.x;
    const int t = threadIdx.x;
    const int lane = t & 31;
    const float* row = g_simi + (size_t)e * N_NODES;

    #pragma unroll 4
    for (int i = 0; i < 32; i++) {
        unsigned b = __float_as_uint(row[i * 256 + t]);
        su[i * 256 + t] = (b & 0x80000000u) ? ~b : (b | 0x80000000u);
    }
    if (t == 0) { s_r = KK_RANK; s_above = 0; }
    __syncthreads();

    unsigned prefix = 0, pmask = 0;
    for (int level = 0; level < 4; level++) {
        int shift = 24 - 8 * level;
        hist[t] = 0;
        __syncthreads();
        #pragma unroll 4
        for (int i = 0; i < 32; i++) {
            unsigned u = su[i * 256 + t];
            if ((u & pmask) == prefix) atomicAdd(&hist[(u >> shift) & 0xFFu], 1u);
        }
        __syncthreads();
        if (t < 32) {
            unsigned h[8], loc[8];
            #pragma unroll
            for (int j = 0; j < 8; j++) h[j] = hist[8 * lane + j];
            unsigned run = 0;
            #pragma unroll
            for (int j = 7; j >= 0; j--) { run += h[j]; loc[j] = run; }
            unsigned suf = run;
            #pragma unroll
            for (int off = 1; off < 32; off <<= 1) {
                unsigned v = __shfl_down_sync(0xFFFFFFFFu, suf, off);
                if (lane + off < 32) suf += v;
            }
            unsigned beyond = suf - run;
            #pragma unroll
            for (int j = 0; j < 8; j++) sfx[8 * lane + j] = loc[j] + beyond;
        }
        __syncthreads();

        const unsigned r_cur = s_r;
        const unsigned nxt   = (t < 255) ? sfx[t + 1] : 0u;
        const bool winner    = (sfx[t] >= r_cur) && (nxt < r_cur);
        __syncthreads();
        if (winner) {
            s_bin = (unsigned)t;
            s_r = r_cur - nxt;
            s_above += nxt;
        }
        __syncthreads();
        prefix |= (s_bin << shift);
        pmask  |= (0xFFu << shift);
        __syncthreads();
    }

    const unsigned thr = prefix;
    const unsigned de  = s_above;

    unsigned v = 0;
    #pragma unroll
    for (int b = 0; b < 32; b++)
        v |= (su[32 * t + b] > thr) ? (1u << b) : 0u;
    g_Hbt[t * E_EDGES + e] = v;

    if (t == 0 && de != DE_NOM) {
        int idx = atomicAdd(&g_nDev, 1);
        g_devE[idx] = e; g_devDE[idx] = (int)de;
    }
}

// =====================================================================
// Kernel 3: bit transpose -> g_Hn[n][32] + s8 g_H8[n][e] + DV2
// =====================================================================
__global__ __launch_bounds__(256) void k_pack_dv()
{
    const int w = blockIdx.x;
    const int t = threadIdx.x;
    const int warp = t >> 5, lane = t & 31;
    __shared__ int s_cnt[32];
    if (t < 32) s_cnt[t] = 0;
    __syncthreads();

    int myCnt = 0;
    #pragma unroll
    for (int i = 0; i < 4; i++) {
        int ew = warp + 8 * i;
        int e  = ew * 32 + lane;
        unsigned v = g_Hbt[w * E_EDGES + e];
        #pragma unroll
        for (int b = 0; b < 32; b++) {
            g_H8[(size_t)(w * 32 + b) * E_EDGES + e] = (unsigned char)((v >> b) & 1u);
            unsigned word = __ballot_sync(0xFFFFFFFFu, (v >> b) & 1u);
            if (lane == b) {
                g_Hn[(size_t)(w * 32 + b) * 32 + ew] = word;
                myCnt += __popc(word);
            }
        }
    }
    atomicAdd(&s_cnt[lane], myCnt);
    __syncthreads();
    if (t < 32) g_DV2[w * 32 + t] = rsqrtf((float)s_cnt[t]);
}

// =====================================================================
// Kernel 4: O = H^T H — WARP-SPECIALIZED hybrid:
//   warps 0-7 : s8 IMMA, cols 0..63   (tensor pipe, 8 indep frags/warp)
//   warps 8-15: CSA popcount, cols 64..127 (alu pipe, R12 loop)
// =====================================================================
#define TSTR 132
#define GSTR 144
#define S8A_BYTES (128 * GSTR)           // 18432 per buffer
#define S8B_BYTES (64  * GSTR)           // 9216 per buffer

__global__ __launch_bounds__(512, 1) void k_gemm(float* __restrict__ G)
{
    int b = blockIdx.x;
    int bi = (int)(64.5f - sqrtf(64.5f * 64.5f - 2.0f * (float)b));
    while (64 * bi - bi * (bi - 1) / 2 > b) bi--;
    while (64 * (bi + 1) - (bi + 1) * bi / 2 <= b) bi++;
    const int bj = bi + (b - (64 * bi - bi * (bi - 1) / 2));

    extern __shared__ char dynsm[];
    char*     s8A = dynsm;                                   // 2 x 18432
    char*     s8B = dynsm + 2 * S8A_BYTES;                   // 2 x 9216
    unsigned* mA  = (unsigned*)(dynsm + 2 * S8A_BYTES + 2 * S8B_BYTES); // [32][128]
    unsigned* mB  = mA + 32 * 128;                           // [32][64] (cols 64..127)
    float*    sT  = (float*)dynsm;                           // [128][TSTR] (reuse)

    const int i0 = bi * 128, j0 = bj * 128;
    const int tid = threadIdx.x;
    const int lane = tid & 31, warp = tid >> 5;
    const bool isIMMA = (warp < 8);

    // -------- cp.async stage loader (s8 from g_H8) --------
    const unsigned s8Abase = smem_u32(s8A), s8Bbase = smem_u32(s8B);
    auto ISSUE = [&](int s, int buf) {
        const int e0 = s * 128;
        #pragma unroll
        for (int u = 0; u < 2; u++) {                        // A: 128 rows x 128B
            int idx = tid + u * 512;
            int row = idx >> 3, ch = (idx & 7) << 4;
            CP16(s8Abase + (unsigned)(buf * S8A_BYTES + row * GSTR + ch),
                 g_H8 + (size_t)(i0 + row) * E_EDGES + e0 + ch);
        }
        {                                                    // B: 64 rows x 128B
            int row = tid >> 3, ch = (tid & 7) << 4;
            CP16(s8Bbase + (unsigned)(buf * S8B_BYTES + row * GSTR + ch),
                 g_H8 + (size_t)(j0 + row) * E_EDGES + e0 + ch);
        }
        CP_COMMIT();
    };

    ISSUE(0, 0);
    ISSUE(1, 1);

    // -------- bitmask tiles: mA all 128 rows, mB rows j0+64..j0+127 --------
    #pragma unroll
    for (int u = 0; u < 2; u++) {
        int idx = tid + u * 512;
        int r = idx >> 3, q = (idx & 7) << 2;
        uint4 va = *(const uint4*)(g_Hn + (size_t)(i0 + r) * 32 + q);
        mA[(q+0)*128 + r] = va.x; mA[(q+1)*128 + r] = va.y;
        mA[(q+2)*128 + r] = va.z; mA[(q+3)*128 + r] = va.w;
    }
    {
        int r = tid >> 3, q = (tid & 7) << 2;
        uint4 vb = *(const uint4*)(g_Hn + (size_t)(j0 + 64 + r) * 32 + q);
        mB[(q+0)*64 + r] = vb.x; mB[(q+1)*64 + r] = vb.y;
        mB[(q+2)*64 + r] = vb.z; mB[(q+3)*64 + r] = vb.w;
    }

    // -------- per-role state --------
    // IMMA warps: wm=warp>>2 (0..1), wn=warp&3; rows wm*64+mt*16, cols wn*16+nt*8
    const int wm = (warp >> 2) & 1, wn = warp & 3;
    const int a_row = lane & 15, a_off = (lane >> 4) << 4;
    const int b_row = ((lane >> 4) << 3) + (lane & 7);
    const int b_off = ((lane >> 3) & 1) << 4;
    int cI[4][2][4];
    #pragma unroll
    for (int mt = 0; mt < 4; mt++)
        #pragma unroll
        for (int nt = 0; nt < 2; nt++)
            #pragma unroll
            for (int q2 = 0; q2 < 4; q2++) cI[mt][nt][q2] = 0;

    // CSA warps: w8 = warp-8 (0..7); rows w8 + 8*jm (jm 0..15), cols 64+lane+32*jn
    const int w8 = warp - 8;
    int acc[16][2];
    unsigned ones[16][2];
    #pragma unroll
    for (int jm = 0; jm < 16; jm++)
        #pragma unroll
        for (int jn = 0; jn < 2; jn++) { acc[jm][jn] = 0; ones[jm][jn] = 0u; }

    // -------- mainloop: 8 stages of 128 edges --------
    for (int s = 0; s < 8; s++) {
        if (s == 7) CP_WAIT0(); else CP_WAIT1();
        __syncthreads();
        const int buf = s & 1;

        if (isIMMA) {
            #pragma unroll
            for (int k = 0; k < 4; k++) {
                int koff = k * 32;
                unsigned af[4][4];
                #pragma unroll
                for (int mt = 0; mt < 4; mt++)
                    ldsm4(af[mt][0], af[mt][1], af[mt][2], af[mt][3],
                          s8Abase + (unsigned)(buf * S8A_BYTES +
                              (wm * 64 + mt * 16 + a_row) * GSTR + koff + a_off));
                unsigned bf[4];
                ldsm4(bf[0], bf[1], bf[2], bf[3],
                      s8Bbase + (unsigned)(buf * S8B_BYTES +
                          (wn * 16 + b_row) * GSTR + koff + b_off));
                #pragma unroll
                for (int mt = 0; mt < 4; mt++) {
                    imma(cI[mt][0], af[mt][0], af[mt][1], af[mt][2], af[mt][3], bf[0], bf[1]);
                    imma(cI[mt][1], af[mt][0], af[mt][1], af[mt][2], af[mt][3], bf[2], bf[3]);
                }
            }
        } else {
            #pragma unroll
            for (int half = 0; half < 2; half++) {
                int ew = 4 * s + 2 * half;
                unsigned b0[2], b1[2];
                #pragma unroll
                for (int jn = 0; jn < 2; jn++) {
                    b0[jn] = mB[ ew      * 64 + lane + 32 * jn];
                    b1[jn] = mB[(ew + 1) * 64 + lane + 32 * jn];
                }
                #pragma unroll
                for (int jm = 0; jm < 16; jm++) {
                    unsigned a0 = mA[ ew      * 128 + w8 + 8 * jm];
                    unsigned a1 = mA[(ew + 1) * 128 + w8 + 8 * jm];
                    #pragma unroll
                    for (int jn = 0; jn < 2; jn++) {
                        unsigned t0 = a0 & b0[jn];
                        unsigned t1 = a1 & b1[jn];
                        unsigned o  = ones[jm][jn];
                        ones[jm][jn] = lop3_xor3(o, t0, t1);
                        acc[jm][jn] += __popc(lop3_maj(o, t0, t1));
                    }
                }
            }
        }
        __syncthreads();
        if (s + 2 < 8) ISSUE(s + 2, buf);
    }
    if (!isIMMA) {
        #pragma unroll
        for (int jm = 0; jm < 16; jm++)
            #pragma unroll
            for (int jn = 0; jn < 2; jn++)
                acc[jm][jn] = 2 * acc[jm][jn] + __popc(ones[jm][jn]);
    }
    __syncthreads();   // all smem reads done before sT reuse

    // -------- epilogue --------
    const bool offd = (bi != bj);
    if (isIMMA) {
        int r = lane >> 2, q2 = lane & 3;
        #pragma unroll
        for (int mt = 0; mt < 4; mt++) {
            int rl0 = wm * 64 + mt * 16 + r;
            int rl1 = rl0 + 8;
            float s0 = g_DV2[i0 + rl0] * W0, s1 = g_DV2[i0 + rl1] * W0;
            #pragma unroll
            for (int nt = 0; nt < 2; nt++) {
                int cl = wn * 16 + nt * 8 + 2 * q2;
                float t0 = g_DV2[j0 + cl], t1 = g_DV2[j0 + cl + 1];
                float v00 = (float)cI[mt][nt][0] * s0 * t0;
                float v01 = (float)cI[mt][nt][1] * s0 * t1;
                float v10 = (float)cI[mt][nt][2] * s1 * t0;
                float v11 = (float)cI[mt][nt][3] * s1 * t1;
                *(float2*)&G[(size_t)(i0 + rl0) * N_NODES + j0 + cl] = make_float2(v00, v01);
                *(float2*)&G[(size_t)(i0 + rl1) * N_NODES + j0 + cl] = make_float2(v10, v11);
                if (offd) {
                    sT[(cl    ) * TSTR + rl0] = v00;
                    sT[(cl + 1) * TSTR + rl0] = v01;
                    sT[(cl    ) * TSTR + rl1] = v10;
                    sT[(cl + 1) * TSTR + rl1] = v11;
                }
            }
        }
    } else {
        #pragma unroll
        for (int jm = 0; jm < 16; jm++) {
            int rl = w8 + 8 * jm;
            float si = g_DV2[i0 + rl] * W0;
            #pragma unroll
            for (int jn = 0; jn < 2; jn++) {
                int cl = 64 + lane + 32 * jn;
                float v = (float)acc[jm][jn] * si * g_DV2[j0 + cl];
                G[(size_t)(i0 + rl) * N_NODES + j0 + cl] = v;
                if (offd) sT[cl * TSTR + rl] = v;
            }
        }
    }
    if (offd) {
        __syncthreads();
        #pragma unroll
        for (int t2 = tid; t2 < 4096; t2 += 512) {
            int jr = t2 >> 5, ic = (t2 & 31) << 2;
            float4 v = *(const float4*)&sT[jr * TSTR + ic];
            *(float4*)&G[(size_t)(j0 + jr) * N_NODES + i0 + ic] = v;
        }
    }
}

// =====================================================================
// Kernel 5: exact correction for deviant edges (de != 818); usually no-op
// =====================================================================
__global__ __launch_bounds__(256) void k_fix(float* __restrict__ G)
{
    const int d = blockIdx.x;
    if (d >= g_nDev) return;
    const int e = g_devE[d];
    const int de = g_devDE[d];
    const float delta = 1.0f / (float)de - W0;

    __shared__ int mem[2048];
    __shared__ int cnt;
    if (threadIdx.x == 0) cnt = 0;
    __syncthreads();
    for (int n = threadIdx.x; n < N_NODES; n += 256)
        if ((g_Hn[(size_t)n * 32 + (e >> 5)] >> (e & 31)) & 1u) {
            int p = atomicAdd(&cnt, 1); mem[p] = n;
        }
    __syncthreads();
    const int m = cnt;
    for (int idx = threadIdx.x; idx < m * m; idx += 256) {
        int i = mem[idx / m], j = mem[idx % m];
        atomicAdd(&G[(size_t)i * N_NODES + j], delta * g_DV2[i] * g_DV2[j]);
    }
}

// =====================================================================
extern "C" void kernel_launch(void* const* d_in, const int* in_sizes, int n_in,
                              void* d_out, int out_size)
{
    const float* x  = (const float*)d_in[0];
    const int*   y  = (const int*)d_in[1];
    const float* hp = (const float*)d_in[2];
    float* out = (float*)d_out;

    const int smemBytes = 2 * S8A_BYTES + 2 * S8B_BYTES + 32 * 128 * 4 + 32 * 64 * 4; // 79872
    cudaFuncSetAttribute(k_gemm, cudaFuncAttributeMaxDynamicSharedMemorySize, smemBytes);

    k_simi<<<dim3(N_NODES / 128, E_EDGES / 64), 256>>>(x, y, hp);
    k_select<<<E_EDGES, 256>>>();
    k_pack_dv<<<256, 256>>>();
    k_gemm<<<2080, 512, smemBytes>>>(out);
    k_fix<<<128, 256>>>(out);

    size_t gElems = (size_t)N_NODES * N_NODES;
    if ((size_t)out_size >= gElems + (size_t)N_NODES * ZD) {
        cudaMemcpyAsync(out + gElems, x, (size_t)N_NODES * ZD * sizeof(float),
                        cudaMemcpyDeviceToDevice);
    }
}

// round 17
// speedup vs baseline: 1.0133x; 1.0003x over previous
#include <cuda_runtime.h>
#include <cuda_bf16.h>
#include <cstdint>

#define E_EDGES 1024
#define N_NODES 8192
#define ZD      256
#define KK_RANK 819
#define DE_NOM  818
#define W0      (1.0f/818.0f)

// ---- scratch ----
__device__ float         g_simi[(size_t)E_EDGES * N_NODES]; // 32 MB [e][n]
__device__ unsigned      g_Hbt[256 * E_EDGES];               // bitmask [n/32][e]
__device__ unsigned      g_Hn[(size_t)N_NODES * 32];         // node-major bits [n][32]
__device__ unsigned char g_H8[(size_t)N_NODES * E_EDGES];    // s8 {0,1} H^T [n][e]
__device__ float         g_DV2[N_NODES];
__device__ int           g_nDev;
__device__ int           g_devE[E_EDGES];
__device__ int           g_devDE[E_EDGES];

// packed fp32x2 FMA (Blackwell)
__device__ __forceinline__ void ffma2(unsigned long long &d,
                                      unsigned long long a, unsigned long long b)
{
    asm volatile("fma.rn.f32x2 %0, %1, %2, %0;" : "+l"(d) : "l"(a), "l"(b));
}
__device__ __forceinline__ unsigned long long pack2(float v)
{
    unsigned long long r;
    asm("mov.b64 %0, {%1, %1};" : "=l"(r) : "f"(v));
    return r;
}
__device__ __forceinline__ unsigned lop3_xor3(unsigned a, unsigned b, unsigned c)
{
    unsigned d;
    asm("lop3.b32 %0, %1, %2, %3, 0x96;" : "=r"(d) : "r"(a), "r"(b), "r"(c));
    return d;
}
__device__ __forceinline__ unsigned lop3_maj(unsigned a, unsigned b, unsigned c)
{
    unsigned d;
    asm("lop3.b32 %0, %1, %2, %3, 0xE8;" : "=r"(d) : "r"(a), "r"(b), "r"(c));
    return d;
}
__device__ __forceinline__ uint32_t smem_u32(const void* p) {
    uint32_t a;
    asm("{ .reg .u64 t; cvta.to.shared.u64 t, %1; cvt.u32.u64 %0, t; }" : "=r"(a) : "l"(p));
    return a;
}
__device__ __forceinline__ void ldsm4(unsigned &r0, unsigned &r1,
                                      unsigned &r2, unsigned &r3, unsigned a)
{
    asm volatile("ldmatrix.sync.aligned.m8n8.x4.shared.b16 {%0,%1,%2,%3}, [%4];"
                 : "=r"(r0), "=r"(r1), "=r"(r2), "=r"(r3) : "r"(a));
}
__device__ __forceinline__ void imma(int c[4], unsigned a0, unsigned a1,
                                     unsigned a2, unsigned a3, unsigned b0, unsigned b1)
{
    asm volatile("mma.sync.aligned.m16n8k32.row.col.s32.s8.s8.s32 "
                 "{%0,%1,%2,%3},{%4,%5,%6,%7},{%8,%9},{%0,%1,%2,%3};"
                 : "+r"(c[0]), "+r"(c[1]), "+r"(c[2]), "+r"(c[3])
                 : "r"(a0), "r"(a1), "r"(a2), "r"(a3), "r"(b0), "r"(b1));
}
#define CP16(dst, src) \
    asm volatile("cp.async.cg.shared.global [%0], [%1], 16;" :: "r"(dst), "l"(src) : "memory")
#define CP_COMMIT() asm volatile("cp.async.commit_group;" ::: "memory")
#define CP_WAIT0()  asm volatile("cp.async.wait_group 0;" ::: "memory")
#define CP_WAIT1()  asm volatile("cp.async.wait_group 1;" ::: "memory")

// =====================================================================
// Kernel 1: simi = hyper_clss @ x^T  (fp32, f32x2-packed FMA)
// =====================================================================
__global__ __launch_bounds__(256) void k_simi(
    const float* __restrict__ x, const int* __restrict__ y,
    const float* __restrict__ hp)
{
    if (blockIdx.x == 0 && blockIdx.y == 0 && threadIdx.x == 0) g_nDev = 0;

    __shared__ float As[32][65];
    __shared__ float Bs[32][130];
    const int be = blockIdx.y * 64, bn = blockIdx.x * 128;
    const int tid = threadIdx.x;
    const int ty = tid >> 4, tx = tid & 15;

    unsigned long long acc2[4][4];
    #pragma unroll
    for (int i = 0; i < 4; i++)
        #pragma unroll
        for (int j = 0; j < 4; j++) acc2[i][j] = 0ull;

    for (int k0 = 0; k0 < ZD; k0 += 32) {
        #pragma unroll
        for (int p = 0; p < 2; p++) {
            int idx = tid + p * 256;
            int e = idx >> 3, k4 = (idx & 7) << 2;
            int ge = be + e;
            int row = y[ge >> 4] * 16 + (ge & 15);
            float4 v = *(const float4*)(hp + (size_t)row * ZD + k0 + k4);
            As[k4+0][e] = v.x; As[k4+1][e] = v.y; As[k4+2][e] = v.z; As[k4+3][e] = v.w;
        }
        #pragma unroll
        for (int p = 0; p < 4; p++) {
            int idx = tid + p * 256;
            int n = idx >> 3, k4 = (idx & 7) << 2;
            float4 v = *(const float4*)(x + (size_t)(bn + n) * ZD + k0 + k4);
            Bs[k4+0][n] = v.x; Bs[k4+1][n] = v.y; Bs[k4+2][n] = v.z; Bs[k4+3][n] = v.w;
        }
        __syncthreads();
        #pragma unroll
        for (int k = 0; k < 32; k++) {
            unsigned long long ad[4], bd[4];
            #pragma unroll
            for (int mi = 0; mi < 4; mi++) ad[mi] = pack2(As[k][ty + 16 * mi]);
            #pragma unroll
            for (int nj = 0; nj < 4; nj++)
                bd[nj] = *(const unsigned long long*)&Bs[k][2 * tx + 32 * nj];
            #pragma unroll
            for (int mi = 0; mi < 4; mi++)
                #pragma unroll
                for (int nj = 0; nj < 4; nj++)
                    ffma2(acc2[mi][nj], ad[mi], bd[nj]);
        }
        __syncthreads();
    }
    #pragma unroll
    for (int mi = 0; mi < 4; mi++)
        #pragma unroll
        for (int nj = 0; nj < 4; nj++) {
            unsigned lo = (unsigned)(acc2[mi][nj] & 0xFFFFFFFFull);
            unsigned hi = (unsigned)(acc2[mi][nj] >> 32);
            float2 v = make_float2(__uint_as_float(lo), __uint_as_float(hi));
            *(float2*)&g_simi[(size_t)(be + ty + 16 * mi) * N_NODES + bn + 2 * tx + 32 * nj] = v;
        }
}

// =====================================================================
// Kernel 2: exact radix select (race-free winner update)
// =====================================================================
__global__ __launch_bounds__(256) void k_select()
{
    __shared__ unsigned su[N_NODES];
    __shared__ unsigned hist[256];
    __shared__ unsigned sfx[256];
    __shared__ unsigned s_bin, s_r, s_above;

    const int e = blockIdx.x;
    const int t = threadIdx.x;
    const int lane = t & 31;
    const float* row = g_simi + (size_t)e * N_NODES;

    #pragma unroll 4
    for (int i = 0; i < 32; i++) {
        unsigned b = __float_as_uint(row[i * 256 + t]);
        su[i * 256 + t] = (b & 0x80000000u) ? ~b : (b | 0x80000000u);
    }
    if (t == 0) { s_r = KK_RANK; s_above = 0; }
    __syncthreads();

    unsigned prefix = 0, pmask = 0;
    for (int level = 0; level < 4; level++) {
        int shift = 24 - 8 * level;
        hist[t] = 0;
        __syncthreads();
        #pragma unroll 4
        for (int i = 0; i < 32; i++) {
            unsigned u = su[i * 256 + t];
            if ((u & pmask) == prefix) atomicAdd(&hist[(u >> shift) & 0xFFu], 1u);
        }
        __syncthreads();
        if (t < 32) {
            unsigned h[8], loc[8];
            #pragma unroll
            for (int j = 0; j < 8; j++) h[j] = hist[8 * lane + j];
            unsigned run = 0;
            #pragma unroll
            for (int j = 7; j >= 0; j--) { run += h[j]; loc[j] = run; }
            unsigned suf = run;
            #pragma unroll
            for (int off = 1; off < 32; off <<= 1) {
                unsigned v = __shfl_down_sync(0xFFFFFFFFu, suf, off);
                if (lane + off < 32) suf += v;
            }
            unsigned beyond = suf - run;
            #pragma unroll
            for (int j = 0; j < 8; j++) sfx[8 * lane + j] = loc[j] + beyond;
        }
        __syncthreads();

        const unsigned r_cur = s_r;
        const unsigned nxt   = (t < 255) ? sfx[t + 1] : 0u;
        const bool winner    = (sfx[t] >= r_cur) && (nxt < r_cur);
        __syncthreads();
        if (winner) {
            s_bin = (unsigned)t;
            s_r = r_cur - nxt;
            s_above += nxt;
        }
        __syncthreads();
        prefix |= (s_bin << shift);
        pmask  |= (0xFFu << shift);
        __syncthreads();
    }

    const unsigned thr = prefix;
    const unsigned de  = s_above;

    unsigned v = 0;
    #pragma unroll
    for (int b = 0; b < 32; b++)
        v |= (su[32 * t + b] > thr) ? (1u << b) : 0u;
    g_Hbt[t * E_EDGES + e] = v;

    if (t == 0 && de != DE_NOM) {
        int idx = atomicAdd(&g_nDev, 1);
        g_devE[idx] = e; g_devDE[idx] = (int)de;
    }
}

// =====================================================================
// Kernel 3: bit transpose -> g_Hn[n][32] + s8 g_H8[n][e] + DV2
// =====================================================================
__global__ __launch_bounds__(256) void k_pack_dv()
{
    const int w = blockIdx.x;
    const int t = threadIdx.x;
    const int warp = t >> 5, lane = t & 31;
    __shared__ int s_cnt[32];
    if (t < 32) s_cnt[t] = 0;
    __syncthreads();

    int myCnt = 0;
    #pragma unroll
    for (int i = 0; i < 4; i++) {
        int ew = warp + 8 * i;
        int e  = ew * 32 + lane;
        unsigned v = g_Hbt[w * E_EDGES + e];
        #pragma unroll
        for (int b = 0; b < 32; b++) {
            g_H8[(size_t)(w * 32 + b) * E_EDGES + e] = (unsigned char)((v >> b) & 1u);
            unsigned word = __ballot_sync(0xFFFFFFFFu, (v >> b) & 1u);
            if (lane == b) {
                g_Hn[(size_t)(w * 32 + b) * 32 + ew] = word;
                myCnt += __popc(word);
            }
        }
    }
    atomicAdd(&s_cnt[lane], myCnt);
    __syncthreads();
    if (t < 32) g_DV2[w * 32 + t] = rsqrtf((float)s_cnt[t]);
}

// =====================================================================
// Kernel 4: O = H^T H — WARP-SPECIALIZED hybrid, PRIORITY-SWAPPED:
//   warps 8-15: s8 IMMA, cols 0..63   (HIGH wid = issue priority)
//   warps 0-7 : CSA popcount, cols 64..127 (fills leftover slots)
// =====================================================================
#define TSTR 132
#define GSTR 144
#define S8A_BYTES (128 * GSTR)           // 18432 per buffer
#define S8B_BYTES (64  * GSTR)           // 9216 per buffer

__global__ __launch_bounds__(512, 1) void k_gemm(float* __restrict__ G)
{
    int b = blockIdx.x;
    int bi = (int)(64.5f - sqrtf(64.5f * 64.5f - 2.0f * (float)b));
    while (64 * bi - bi * (bi - 1) / 2 > b) bi--;
    while (64 * (bi + 1) - (bi + 1) * bi / 2 <= b) bi++;
    const int bj = bi + (b - (64 * bi - bi * (bi - 1) / 2));

    extern __shared__ char dynsm[];
    char*     s8A = dynsm;                                   // 2 x 18432
    char*     s8B = dynsm + 2 * S8A_BYTES;                   // 2 x 9216
    unsigned* mA  = (unsigned*)(dynsm + 2 * S8A_BYTES + 2 * S8B_BYTES); // [32][128]
    unsigned* mB  = mA + 32 * 128;                           // [32][64] (cols 64..127)
    float*    sT  = (float*)dynsm;                           // [128][TSTR] (reuse)

    const int i0 = bi * 128, j0 = bj * 128;
    const int tid = threadIdx.x;
    const int lane = tid & 31, warp = tid >> 5;
    const bool isIMMA = (warp >= 8);       // HIGH-wid warps drive the tensor pipe

    // -------- cp.async stage loader (s8 from g_H8) --------
    const unsigned s8Abase = smem_u32(s8A), s8Bbase = smem_u32(s8B);
    auto ISSUE = [&](int s, int buf) {
        const int e0 = s * 128;
        #pragma unroll
        for (int u = 0; u < 2; u++) {                        // A: 128 rows x 128B
            int idx = tid + u * 512;
            int row = idx >> 3, ch = (idx & 7) << 4;
            CP16(s8Abase + (unsigned)(buf * S8A_BYTES + row * GSTR + ch),
                 g_H8 + (size_t)(i0 + row) * E_EDGES + e0 + ch);
        }
        {                                                    // B: 64 rows x 128B
            int row = tid >> 3, ch = (tid & 7) << 4;
            CP16(s8Bbase + (unsigned)(buf * S8B_BYTES + row * GSTR + ch),
                 g_H8 + (size_t)(j0 + row) * E_EDGES + e0 + ch);
        }
        CP_COMMIT();
    };

    ISSUE(0, 0);
    ISSUE(1, 1);

    // -------- bitmask tiles: mA all 128 rows, mB rows j0+64..j0+127 --------
    #pragma unroll
    for (int u = 0; u < 2; u++) {
        int idx = tid + u * 512;
        int r = idx >> 3, q = (idx & 7) << 2;
        uint4 va = *(const uint4*)(g_Hn + (size_t)(i0 + r) * 32 + q);
        mA[(q+0)*128 + r] = va.x; mA[(q+1)*128 + r] = va.y;
        mA[(q+2)*128 + r] = va.z; mA[(q+3)*128 + r] = va.w;
    }
    {
        int r = tid >> 3, q = (tid & 7) << 2;
        uint4 vb = *(const uint4*)(g_Hn + (size_t)(j0 + 64 + r) * 32 + q);
        mB[(q+0)*64 + r] = vb.x; mB[(q+1)*64 + r] = vb.y;
        mB[(q+2)*64 + r] = vb.z; mB[(q+3)*64 + r] = vb.w;
    }

    // -------- per-role state --------
    // IMMA warps (8-15): w=warp-8; wm=(w>>2)&1, wn=w&3
    const int wI = warp - 8;
    const int wm = (wI >> 2) & 1, wn = wI & 3;
    const int a_row = lane & 15, a_off = (lane >> 4) << 4;
    const int b_row = ((lane >> 4) << 3) + (lane & 7);
    const int b_off = ((lane >> 3) & 1) << 4;
    int cI[4][2][4];
    #pragma unroll
    for (int mt = 0; mt < 4; mt++)
        #pragma unroll
        for (int nt = 0; nt < 2; nt++)
            #pragma unroll
            for (int q2 = 0; q2 < 4; q2++) cI[mt][nt][q2] = 0;

    // CSA warps (0-7): rows w8 + 8*jm (jm 0..15), cols 64+lane+32*jn
    const int w8 = warp;
    int acc[16][2];
    unsigned ones[16][2];
    #pragma unroll
    for (int jm = 0; jm < 16; jm++)
        #pragma unroll
        for (int jn = 0; jn < 2; jn++) { acc[jm][jn] = 0; ones[jm][jn] = 0u; }

    // -------- mainloop: 8 stages of 128 edges --------
    for (int s = 0; s < 8; s++) {
        if (s == 7) CP_WAIT0(); else CP_WAIT1();
        __syncthreads();
        const int buf = s & 1;

        if (isIMMA) {
            #pragma unroll
            for (int k = 0; k < 4; k++) {
                int koff = k * 32;
                unsigned af[4][4];
                #pragma unroll
                for (int mt = 0; mt < 4; mt++)
                    ldsm4(af[mt][0], af[mt][1], af[mt][2], af[mt][3],
                          s8Abase + (unsigned)(buf * S8A_BYTES +
                              (wm * 64 + mt * 16 + a_row) * GSTR + koff + a_off));
                unsigned bf[4];
                ldsm4(bf[0], bf[1], bf[2], bf[3],
                      s8Bbase + (unsigned)(buf * S8B_BYTES +
                          (wn * 16 + b_row) * GSTR + koff + b_off));
                #pragma unroll
                for (int mt = 0; mt < 4; mt++) {
                    imma(cI[mt][0], af[mt][0], af[mt][1], af[mt][2], af[mt][3], bf[0], bf[1]);
                    imma(cI[mt][1], af[mt][0], af[mt][1], af[mt][2], af[mt][3], bf[2], bf[3]);
                }
            }
        } else {
            #pragma unroll
            for (int half = 0; half < 2; half++) {
                int ew = 4 * s + 2 * half;
                unsigned b0[2], b1[2];
                #pragma unroll
                for (int jn = 0; jn < 2; jn++) {
                    b0[jn] = mB[ ew      * 64 + lane + 32 * jn];
                    b1[jn] = mB[(ew + 1) * 64 + lane + 32 * jn];
                }
                #pragma unroll
                for (int jm = 0; jm < 16; jm++) {
                    unsigned a0 = mA[ ew      * 128 + w8 + 8 * jm];
                    unsigned a1 = mA[(ew + 1) * 128 + w8 + 8 * jm];
                    #pragma unroll
                    for (int jn = 0; jn < 2; jn++) {
                        unsigned t0 = a0 & b0[jn];
                        unsigned t1 = a1 & b1[jn];
                        unsigned o  = ones[jm][jn];
                        ones[jm][jn] = lop3_xor3(o, t0, t1);
                        acc[jm][jn] += __popc(lop3_maj(o, t0, t1));
                    }
                }
            }
        }
        __syncthreads();
        if (s + 2 < 8) ISSUE(s + 2, buf);
    }
    if (!isIMMA) {
        #pragma unroll
        for (int jm = 0; jm < 16; jm++)
            #pragma unroll
            for (int jn = 0; jn < 2; jn++)
                acc[jm][jn] = 2 * acc[jm][jn] + __popc(ones[jm][jn]);
    }
    __syncthreads();   // all smem reads done before sT reuse

    // -------- epilogue --------
    const bool offd = (bi != bj);
    if (isIMMA) {
        int r = lane >> 2, q2 = lane & 3;
        #pragma unroll
        for (int mt = 0; mt < 4; mt++) {
            int rl0 = wm * 64 + mt * 16 + r;
            int rl1 = rl0 + 8;
            float s0 = g_DV2[i0 + rl0] * W0, s1 = g_DV2[i0 + rl1] * W0;
            #pragma unroll
            for (int nt = 0; nt < 2; nt++) {
                int cl = wn * 16 + nt * 8 + 2 * q2;
                float t0 = g_DV2[j0 + cl], t1 = g_DV2[j0 + cl + 1];
                float v00 = (float)cI[mt][nt][0] * s0 * t0;
                float v01 = (float)cI[mt][nt][1] * s0 * t1;
                float v10 = (float)cI[mt][nt][2] * s1 * t0;
                float v11 = (float)cI[mt][nt][3] * s1 * t1;
                *(float2*)&G[(size_t)(i0 + rl0) * N_NODES + j0 + cl] = make_float2(v00, v01);
                *(float2*)&G[(size_t)(i0 + rl1) * N_NODES + j0 + cl] = make_float2(v10, v11);
                if (offd) {
                    sT[(cl    ) * TSTR + rl0] = v00;
                    sT[(cl + 1) * TSTR + rl0] = v01;
                    sT[(cl    ) * TSTR + rl1] = v10;
                    sT[(cl + 1) * TSTR + rl1] = v11;
                }
            }
        }
    } else {
        #pragma unroll
        for (int jm = 0; jm < 16; jm++) {
            int rl = w8 + 8 * jm;
            float si = g_DV2[i0 + rl] * W0;
            #pragma unroll
            for (int jn = 0; jn < 2; jn++) {
                int cl = 64 + lane + 32 * jn;
                float v = (float)acc[jm][jn] * si * g_DV2[j0 + cl];
                G[(size_t)(i0 + rl) * N_NODES + j0 + cl] = v;
                if (offd) sT[cl * TSTR + rl] = v;
            }
        }
    }
    if (offd) {
        __syncthreads();
        #pragma unroll
        for (int t2 = tid; t2 < 4096; t2 += 512) {
            int jr = t2 >> 5, ic = (t2 & 31) << 2;
            float4 v = *(const float4*)&sT[jr * TSTR + ic];
            *(float4*)&G[(size_t)(j0 + jr) * N_NODES + i0 + ic] = v;
        }
    }
}

// =====================================================================
// Kernel 5: exact correction for deviant edges (de != 818); usually no-op
// =====================================================================
__global__ __launch_bounds__(256) void k_fix(float* __restrict__ G)
{
    const int d = blockIdx.x;
    if (d >= g_nDev) return;
    const int e = g_devE[d];
    const int de = g_devDE[d];
    const float delta = 1.0f / (float)de - W0;

    __shared__ int mem[2048];
    __shared__ int cnt;
    if (threadIdx.x == 0) cnt = 0;
    __syncthreads();
    for (int n = threadIdx.x; n < N_NODES; n += 256)
        if ((g_Hn[(size_t)n * 32 + (e >> 5)] >> (e & 31)) & 1u) {
            int p = atomicAdd(&cnt, 1); mem[p] = n;
        }
    __syncthreads();
    const int m = cnt;
    for (int idx = threadIdx.x; idx < m * m; idx += 256) {
        int i = mem[idx / m], j = mem[idx % m];
        atomicAdd(&G[(size_t)i * N_NODES + j], delta * g_DV2[i] * g_DV2[j]);
    }
}

// =====================================================================
extern "C" void kernel_launch(void* const* d_in, const int* in_sizes, int n_in,
                              void* d_out, int out_size)
{
    const float* x  = (const float*)d_in[0];
    const int*   y  = (const int*)d_in[1];
    const float* hp = (const float*)d_in[2];
    float* out = (float*)d_out;

    const int smemBytes = 2 * S8A_BYTES + 2 * S8B_BYTES + 32 * 128 * 4 + 32 * 64 * 4; // 79872
    cudaFuncSetAttribute(k_gemm, cudaFuncAttributeMaxDynamicSharedMemorySize, smemBytes);

    k_simi<<<dim3(N_NODES / 128, E_EDGES / 64), 256>>>(x, y, hp);
    k_select<<<E_EDGES, 256>>>();
    k_pack_dv<<<256, 256>>>();
    k_gemm<<<2080, 512, smemBytes>>>(out);
    k_fix<<<128, 256>>>(out);

    size_t gElems = (size_t)N_NODES * N_NODES;
    if ((size_t)out_size >= gElems + (size_t)N_NODES * ZD) {
        cudaMemcpyAsync(out + gElems, x, (size_t)N_NODES * ZD * sizeof(float),
                        cudaMemcpyDeviceToDevice);
    }
}